// round 2
// baseline (speedup 1.0000x reference)
#include <cuda_runtime.h>

// Problem constants
#define N_ROWS   16384
#define IN_DIM   64
#define HID      256
#define OUT_DIM  64
#define NEXP     256
#define TM       64      // rows per tile
#define TILES_Y  8       // max tiles per expert (rows<=512; binomial max ~90, huge margin)
#define THREADS  256

typedef unsigned long long ULL;

// ---------------- scratch (no allocations allowed) ----------------
__device__ int g_off[NEXP + 1];
__device__ int g_cur[NEXP];
__device__ int g_perm[N_ROWS];

// ---------------- small helpers ----------------
__device__ __forceinline__ void fma2(ULL &acc, ULL a, ULL b) {
    asm("fma.rn.f32x2 %0, %1, %2, %0;" : "+l"(acc) : "l"(a), "l"(b));
}
__device__ __forceinline__ ULL dup2(float x) {
    ULL r; asm("mov.b64 %0, {%1, %1};" : "=l"(r) : "f"(x)); return r;
}
__device__ __forceinline__ float2 unpack2(ULL v) {
    float2 r;
    r.x = __uint_as_float((unsigned)(v & 0xFFFFFFFFull));
    r.y = __uint_as_float((unsigned)(v >> 32));
    return r;
}
// tanh(x) = sign(x) * (1 - t)/(1 + t), t = exp(-2|x|)  (t in (0,1], no overflow)
__device__ __forceinline__ float fast_tanh(float x) {
    float ax = fabsf(x);
    float t = __expf(-2.0f * ax);
    float r = __fdividef(1.0f - t, 1.0f + t);
    return copysignf(r, x);
}

// ---------------- grouping kernels ----------------
__global__ void k_zero() { g_cur[threadIdx.x] = 0; }

__global__ void k_hist(const int* __restrict__ ind) {
    int i = blockIdx.x * blockDim.x + threadIdx.x;
    atomicAdd(&g_cur[ind[i]], 1);
}

__global__ void k_scan() {
    __shared__ int s[NEXP];
    int t = threadIdx.x;
    int c = g_cur[t];
    s[t] = c;
    __syncthreads();
    #pragma unroll
    for (int d = 1; d < NEXP; d <<= 1) {
        int v = (t >= d) ? s[t - d] : 0;
        __syncthreads();
        s[t] += v;
        __syncthreads();
    }
    int off = s[t] - c;           // exclusive
    g_off[t] = off;
    g_cur[t] = off;               // scatter cursor
    if (t == NEXP - 1) g_off[NEXP] = s[t];
}

__global__ void k_scatter(const int* __restrict__ ind) {
    int i = blockIdx.x * blockDim.x + threadIdx.x;
    int pos = atomicAdd(&g_cur[ind[i]], 1);
    g_perm[pos] = i;
}

// ---------------- fused MLP microkernel ----------------
// Accumulate 64 K-steps into acc[8 rows][4 output-pairs].
// sX: activations [m][LDX] (warp-broadcast reads); sW: weights transposed [k][256].
template <int LDX>
__device__ __forceinline__ void gemm64(const float* __restrict__ sX,
                                       const float* __restrict__ sW,
                                       ULL acc[8][4], int mg, int og) {
    #pragma unroll 2
    for (int k = 0; k < 64; k += 4) {
        float4 xr[8];
        #pragma unroll
        for (int i = 0; i < 8; i++)
            xr[i] = *(const float4*)&sX[(mg * 8 + i) * LDX + k];
        #pragma unroll
        for (int kk = 0; kk < 4; kk++) {
            ulonglong2 wA = *(const ulonglong2*)&sW[(k + kk) * 256 + og * 4];
            ulonglong2 wB = *(const ulonglong2*)&sW[(k + kk) * 256 + og * 4 + 128];
            #pragma unroll
            for (int i = 0; i < 8; i++) {
                float xv = (kk == 0) ? xr[i].x : (kk == 1) ? xr[i].y
                         : (kk == 2) ? xr[i].z : xr[i].w;
                ULL x2 = dup2(xv);
                fma2(acc[i][0], x2, wA.x);
                fma2(acc[i][1], x2, wA.y);
                fma2(acc[i][2], x2, wB.x);
                fma2(acc[i][3], x2, wB.y);
            }
        }
    }
}

__global__ __launch_bounds__(THREADS, 1)
void k_mlp(const float* __restrict__ Xg,
           const float* __restrict__ W1, const float* __restrict__ B1,
           const float* __restrict__ W2, const float* __restrict__ B2,
           const float* __restrict__ W3, const float* __restrict__ B3,
           float* __restrict__ Og) {
    int e = blockIdx.x;
    int start = g_off[e], end = g_off[e + 1];
    int rstart = start + (int)blockIdx.y * TM;
    if (rstart >= end) return;
    int mrows = min(TM, end - rstart);

    extern __shared__ float sm[];
    float* sH1 = sm;                  // [TM][256]  h1
    float* sB  = sm + TM * 256;       // xs [TM][64], later h2 [TM][256]
    float* sW  = sm + 2 * TM * 256;   // weight stage: [64][256] or [256][64]

    int tid = threadIdx.x;
    int og = tid & 31;                // output lane group (warp lanes)
    int mg = tid >> 5;                // row group (one per warp)

    // ---- stage x rows (zero-pad m >= mrows) ----
    {
        int m = tid >> 2;             // 0..63
        int fq = tid & 3;             // quarter of the 64-float row
        float4 vals[4];
        if (m < mrows) {
            int n = g_perm[rstart + m];
            const float4* src = (const float4*)(Xg + (size_t)n * IN_DIM) + fq * 4;
            #pragma unroll
            for (int u = 0; u < 4; u++) vals[u] = src[u];
        } else {
            #pragma unroll
            for (int u = 0; u < 4; u++) vals[u] = make_float4(0.f, 0.f, 0.f, 0.f);
        }
        float4* dst = (float4*)sB + tid * 4;
        #pragma unroll
        for (int u = 0; u < 4; u++) dst[u] = vals[u];
    }
    // ---- stage W1 transposed: sW[k][o], o = tid ----
    {
        const float* wsrc = W1 + ((size_t)e * 256 + tid) * 64;
        #pragma unroll
        for (int k4 = 0; k4 < 64; k4 += 4) {
            float4 v = *(const float4*)(wsrc + k4);
            sW[(k4 + 0) * 256 + tid] = v.x;
            sW[(k4 + 1) * 256 + tid] = v.y;
            sW[(k4 + 2) * 256 + tid] = v.z;
            sW[(k4 + 3) * 256 + tid] = v.w;
        }
    }
    __syncthreads();

    ULL acc[8][4];

    // ---- layer 1: 64 -> 256, tanh ----
    {
        ulonglong2 bA = *(const ulonglong2*)(B1 + (size_t)e * 256 + og * 4);
        ulonglong2 bB = *(const ulonglong2*)(B1 + (size_t)e * 256 + og * 4 + 128);
        #pragma unroll
        for (int i = 0; i < 8; i++) {
            acc[i][0] = bA.x; acc[i][1] = bA.y; acc[i][2] = bB.x; acc[i][3] = bB.y;
        }
        gemm64<64>(sB, sW, acc, mg, og);
        #pragma unroll
        for (int i = 0; i < 8; i++) {
            float2 p0 = unpack2(acc[i][0]), p1 = unpack2(acc[i][1]);
            float2 p2 = unpack2(acc[i][2]), p3 = unpack2(acc[i][3]);
            float4 a = make_float4(fast_tanh(p0.x), fast_tanh(p0.y),
                                   fast_tanh(p1.x), fast_tanh(p1.y));
            float4 b = make_float4(fast_tanh(p2.x), fast_tanh(p2.y),
                                   fast_tanh(p3.x), fast_tanh(p3.y));
            int m = mg * 8 + i;
            *(float4*)&sH1[m * 256 + og * 4] = a;
            *(float4*)&sH1[m * 256 + og * 4 + 128] = b;
        }
    }
    __syncthreads();

    // ---- layer 2: 256 -> 256 in 4 K-chunks, tanh ----
    {
        ulonglong2 bA = *(const ulonglong2*)(B2 + (size_t)e * 256 + og * 4);
        ulonglong2 bB = *(const ulonglong2*)(B2 + (size_t)e * 256 + og * 4 + 128);
        #pragma unroll
        for (int i = 0; i < 8; i++) {
            acc[i][0] = bA.x; acc[i][1] = bA.y; acc[i][2] = bB.x; acc[i][3] = bB.y;
        }
        for (int c = 0; c < 4; c++) {
            const float* wsrc = W2 + ((size_t)e * 256 + tid) * 256 + c * 64;
            #pragma unroll
            for (int k4 = 0; k4 < 64; k4 += 4) {
                float4 v = *(const float4*)(wsrc + k4);
                sW[(k4 + 0) * 256 + tid] = v.x;
                sW[(k4 + 1) * 256 + tid] = v.y;
                sW[(k4 + 2) * 256 + tid] = v.z;
                sW[(k4 + 3) * 256 + tid] = v.w;
            }
            __syncthreads();
            gemm64<256>(sH1 + c * 64, sW, acc, mg, og);
            __syncthreads();
        }
        // tanh -> h2 into sB (xs is dead)
        #pragma unroll
        for (int i = 0; i < 8; i++) {
            float2 p0 = unpack2(acc[i][0]), p1 = unpack2(acc[i][1]);
            float2 p2 = unpack2(acc[i][2]), p3 = unpack2(acc[i][3]);
            float4 a = make_float4(fast_tanh(p0.x), fast_tanh(p0.y),
                                   fast_tanh(p1.x), fast_tanh(p1.y));
            float4 b = make_float4(fast_tanh(p2.x), fast_tanh(p2.y),
                                   fast_tanh(p3.x), fast_tanh(p3.y));
            int m = mg * 8 + i;
            *(float4*)&sB[m * 256 + og * 4] = a;
            *(float4*)&sB[m * 256 + og * 4 + 128] = b;
        }
    }

    // ---- stage W3 transposed: sW[k][64] (k=0..255) ----
    {
        int o = tid & 63;
        int ks = (tid >> 6) * 64;
        const float* wsrc = W3 + ((size_t)e * 64 + o) * 256;
        #pragma unroll
        for (int k4 = ks; k4 < ks + 64; k4 += 4) {
            float4 v = *(const float4*)(wsrc + k4);
            sW[(k4 + 0) * 64 + o] = v.x;
            sW[(k4 + 1) * 64 + o] = v.y;
            sW[(k4 + 2) * 64 + o] = v.z;
            sW[(k4 + 3) * 64 + o] = v.w;
        }
    }
    __syncthreads();

    // ---- layer 3: 256 -> 64, linear, scatter to output ----
    {
        ULL acc3[8];
        ULL b3 = *(const ULL*)(B3 + (size_t)e * 64 + og * 2);
        #pragma unroll
        for (int i = 0; i < 8; i++) acc3[i] = b3;

        #pragma unroll 2
        for (int k = 0; k < 256; k += 4) {
            float4 xr[8];
            #pragma unroll
            for (int i = 0; i < 8; i++)
                xr[i] = *(const float4*)&sB[(mg * 8 + i) * 256 + k];
            #pragma unroll
            for (int kk = 0; kk < 4; kk++) {
                ULL w = *(const ULL*)&sW[(k + kk) * 64 + og * 2];
                #pragma unroll
                for (int i = 0; i < 8; i++) {
                    float xv = (kk == 0) ? xr[i].x : (kk == 1) ? xr[i].y
                             : (kk == 2) ? xr[i].z : xr[i].w;
                    fma2(acc3[i], dup2(xv), w);
                }
            }
        }
        #pragma unroll
        for (int i = 0; i < 8; i++) {
            int m = mg * 8 + i;
            if (m < mrows) {
                int n = g_perm[rstart + m];
                *(ULL*)&Og[(size_t)n * OUT_DIM + og * 2] = acc3[i];
            }
        }
    }
}

// ---------------- launch ----------------
extern "C" void kernel_launch(void* const* d_in, const int* in_sizes, int n_in,
                              void* d_out, int out_size) {
    const float* x  = (const float*)d_in[0];
    const int*   ind = (const int*)d_in[1];
    const float* W1 = (const float*)d_in[2];
    const float* b1 = (const float*)d_in[3];
    const float* W2 = (const float*)d_in[4];
    const float* b2 = (const float*)d_in[5];
    const float* Wl = (const float*)d_in[6];
    const float* bl = (const float*)d_in[7];
    float* out = (float*)d_out;

    (void)in_sizes; (void)n_in; (void)out_size;

    static_assert(3 * TM * 256 * sizeof(float) == 196608, "smem size");
    cudaFuncSetAttribute(k_mlp, cudaFuncAttributeMaxDynamicSharedMemorySize, 196608);

    k_zero<<<1, NEXP>>>();
    k_hist<<<N_ROWS / THREADS, THREADS>>>(ind);
    k_scan<<<1, NEXP>>>();
    k_scatter<<<N_ROWS / THREADS, THREADS>>>(ind);
    k_mlp<<<dim3(NEXP, TILES_Y), THREADS, 196608>>>(x, W1, b1, W2, b2, Wl, bl, out);
}

// round 4
// speedup vs baseline: 1.2207x; 1.2207x over previous
#include <cuda_runtime.h>

// Problem constants
#define N_ROWS   16384
#define IN_DIM   64
#define HID      256
#define OUT_DIM  64
#define NEXP     256
#define CAP      128     // per-expert bucket capacity (binomial max ~90, 8-sigma margin)
#define TM       64      // rows per tile
#define TILES_Y  (CAP / TM)
#define THREADS  256

typedef unsigned long long ULL;

// ---------------- scratch (no allocations allowed) ----------------
__device__ int g_cnt[NEXP];
__device__ int g_bucket[NEXP * CAP];

// ---------------- small helpers ----------------
__device__ __forceinline__ void fma2(ULL &acc, ULL a, ULL b) {
    asm("fma.rn.f32x2 %0, %1, %2, %0;" : "+l"(acc) : "l"(a), "l"(b));
}
__device__ __forceinline__ ULL dup2(float x) {
    ULL r; asm("mov.b64 %0, {%1, %1};" : "=l"(r) : "f"(x)); return r;
}
__device__ __forceinline__ float2 unpack2(ULL v) {
    float2 r;
    r.x = __uint_as_float((unsigned)(v & 0xFFFFFFFFull));
    r.y = __uint_as_float((unsigned)(v >> 32));
    return r;
}
// tanh(x) = sign(x) * (1 - t)/(1 + t), t = exp(-2|x|)  (t in (0,1], no overflow)
__device__ __forceinline__ float fast_tanh(float x) {
    float ax = fabsf(x);
    float t = __expf(-2.0f * ax);
    float r = __fdividef(1.0f - t, 1.0f + t);
    return copysignf(r, x);
}

// ---------------- grouping: single bucket-fill kernel ----------------
__global__ void k_fill(const int* __restrict__ ind) {
    int i = blockIdx.x * blockDim.x + threadIdx.x;
    int e = ind[i];
    int p = atomicAdd(&g_cnt[e], 1);
    if (p < CAP) g_bucket[e * CAP + p] = i;
}

// ---------------- GEMM microkernel ----------------
// Accumulate KK K-steps into acc[8 rows][4 output-pairs].
// sX: activations [m][LDX] (warp-broadcast reads, pre-offset in k); sW: weights [k][256].
template <int KK, int LDX>
__device__ __forceinline__ void gemmk(const float* __restrict__ sX,
                                      const float* __restrict__ sW,
                                      ULL acc[8][4], int mg, int og) {
    #pragma unroll 2
    for (int k = 0; k < KK; k += 4) {
        float4 xr[8];
        #pragma unroll
        for (int i = 0; i < 8; i++)
            xr[i] = *(const float4*)&sX[(mg * 8 + i) * LDX + k];
        #pragma unroll
        for (int kk = 0; kk < 4; kk++) {
            ulonglong2 wA = *(const ulonglong2*)&sW[(k + kk) * 256 + og * 4];
            ulonglong2 wB = *(const ulonglong2*)&sW[(k + kk) * 256 + og * 4 + 128];
            #pragma unroll
            for (int i = 0; i < 8; i++) {
                float xv = (kk == 0) ? xr[i].x : (kk == 1) ? xr[i].y
                         : (kk == 2) ? xr[i].z : xr[i].w;
                ULL x2 = dup2(xv);
                fma2(acc[i][0], x2, wA.x);
                fma2(acc[i][1], x2, wA.y);
                fma2(acc[i][2], x2, wB.x);
                fma2(acc[i][3], x2, wB.y);
            }
        }
    }
}

__global__ __launch_bounds__(THREADS, 1)
void k_mlp(const float* __restrict__ Xg,
           const float* __restrict__ W1, const float* __restrict__ B1,
           const float* __restrict__ W2, const float* __restrict__ B2,
           const float* __restrict__ W3, const float* __restrict__ B3,
           float* __restrict__ Og) {
    int e = blockIdx.x;
    int cnt = min(g_cnt[e], CAP);
    int rs = (int)blockIdx.y * TM;
    if (rs >= cnt) return;
    int mrows = min(TM, cnt - rs);

    extern __shared__ float sm[];
    float* sA = sm;                   // 64KB: h1, then h2 (in-place, own-warp rows only)
    float* sB = sm + TM * 256;        // 64KB: x [64][64] (16KB), then W3 [256][64]
    float* sC = sm + 2 * TM * 256;    // 64KB: W1 [64][256], then W2 double buffer 2x[32][256]

    int tid = threadIdx.x;
    int og = tid & 31;                // output lane
    int mg = tid >> 5;                // row group (one per warp)
    bool wact = (mg * 8 < mrows);     // warp has any real rows

    // ---- stage x rows into sB[64][64] (zero-pad m >= mrows) ----
    {
        int m = tid >> 2;             // 0..63
        int fq = tid & 3;             // quarter of the 64-float row
        float4 vals[4];
        if (m < mrows) {
            int n = g_bucket[e * CAP + rs + m];
            const float4* src = (const float4*)(Xg + (size_t)n * IN_DIM) + fq * 4;
            #pragma unroll
            for (int u = 0; u < 4; u++) vals[u] = src[u];
        } else {
            #pragma unroll
            for (int u = 0; u < 4; u++) vals[u] = make_float4(0.f, 0.f, 0.f, 0.f);
        }
        float4* dst = (float4*)sB + tid * 4;
        #pragma unroll
        for (int u = 0; u < 4; u++) dst[u] = vals[u];
    }
    // ---- stage W1 transposed into sC[k][256] (full 64 k-rows) ----
    {
        const float* wsrc = W1 + ((size_t)e * 256 + tid) * 64;
        #pragma unroll
        for (int k4 = 0; k4 < 64; k4 += 4) {
            float4 v = *(const float4*)(wsrc + k4);
            sC[(k4 + 0) * 256 + tid] = v.x;
            sC[(k4 + 1) * 256 + tid] = v.y;
            sC[(k4 + 2) * 256 + tid] = v.z;
            sC[(k4 + 3) * 256 + tid] = v.w;
        }
    }
    __syncthreads();

    ULL acc[8][4];
    const float* w2base = W2 + ((size_t)e * 256 + tid) * 256;
    float4 pf[8];

    // ---- layer 1: 64 -> 256, tanh -> sA ----
    {
        ulonglong2 bA = *(const ulonglong2*)(B1 + (size_t)e * 256 + og * 4);
        ulonglong2 bB = *(const ulonglong2*)(B1 + (size_t)e * 256 + og * 4 + 128);
        #pragma unroll
        for (int i = 0; i < 8; i++) {
            acc[i][0] = bA.x; acc[i][1] = bA.y; acc[i][2] = bB.x; acc[i][3] = bB.y;
        }
        if (wact) gemmk<64, 64>(sB, sC, acc, mg, og);

        // prefetch W2 chunk 0 (all warps)
        #pragma unroll
        for (int j = 0; j < 8; j++)
            pf[j] = *(const float4*)(w2base + j * 4);

        if (wact) {
            #pragma unroll
            for (int i = 0; i < 8; i++) {
                float2 p0 = unpack2(acc[i][0]), p1 = unpack2(acc[i][1]);
                float2 p2 = unpack2(acc[i][2]), p3 = unpack2(acc[i][3]);
                float4 a = make_float4(fast_tanh(p0.x), fast_tanh(p0.y),
                                       fast_tanh(p1.x), fast_tanh(p1.y));
                float4 b = make_float4(fast_tanh(p2.x), fast_tanh(p2.y),
                                       fast_tanh(p3.x), fast_tanh(p3.y));
                int m = mg * 8 + i;
                *(float4*)&sA[m * 256 + og * 4] = a;
                *(float4*)&sA[m * 256 + og * 4 + 128] = b;
            }
        }
    }
    __syncthreads();   // W1/x reads done, h1 ready

    // STS W2 chunk 0 -> buffer 0
    {
        #pragma unroll
        for (int j = 0; j < 8; j++) {
            int kl = j * 4;
            sC[(kl + 0) * 256 + tid] = pf[j].x;
            sC[(kl + 1) * 256 + tid] = pf[j].y;
            sC[(kl + 2) * 256 + tid] = pf[j].z;
            sC[(kl + 3) * 256 + tid] = pf[j].w;
        }
    }
    __syncthreads();

    // ---- layer 2: 256 -> 256, 8 pipelined chunks of 32 k-rows ----
    {
        ulonglong2 bA = *(const ulonglong2*)(B2 + (size_t)e * 256 + og * 4);
        ulonglong2 bB = *(const ulonglong2*)(B2 + (size_t)e * 256 + og * 4 + 128);
        #pragma unroll
        for (int i = 0; i < 8; i++) {
            acc[i][0] = bA.x; acc[i][1] = bA.y; acc[i][2] = bB.x; acc[i][3] = bB.y;
        }

        int o3 = tid & 63;            // W3 staging role
        int g3 = tid >> 6;
        const float* w3src = W3 + ((size_t)e * 64 + o3) * 256 + g3 * 16;

        #pragma unroll
        for (int c = 0; c < 8; c++) {
            float* cur = sC + (c & 1) * 32 * 256;
            float* nxt = sC + ((c + 1) & 1) * 32 * 256;

            // prefetch next W2 chunk
            if (c < 7) {
                #pragma unroll
                for (int j = 0; j < 8; j++)
                    pf[j] = *(const float4*)(w2base + (c + 1) * 32 + j * 4);
            }
            // prefetch W3 quarter into regs (c = 0..3); x region is dead now
            float4 pw[4];
            if (c < 4) {
                #pragma unroll
                for (int j = 0; j < 4; j++)
                    pw[j] = *(const float4*)(w3src + c * 64 + j * 4);
            }

            if (wact) gemmk<32, 256>(sA + c * 32, cur, acc, mg, og);

            // store W3 quarter into sB[k][64]
            if (c < 4) {
                #pragma unroll
                for (int j = 0; j < 4; j++) {
                    int kb = c * 64 + g3 * 16 + j * 4;
                    sB[(kb + 0) * 64 + o3] = pw[j].x;
                    sB[(kb + 1) * 64 + o3] = pw[j].y;
                    sB[(kb + 2) * 64 + o3] = pw[j].z;
                    sB[(kb + 3) * 64 + o3] = pw[j].w;
                }
            }
            // store next W2 chunk
            if (c < 7) {
                #pragma unroll
                for (int j = 0; j < 8; j++) {
                    int kl = j * 4;
                    nxt[(kl + 0) * 256 + tid] = pf[j].x;
                    nxt[(kl + 1) * 256 + tid] = pf[j].y;
                    nxt[(kl + 2) * 256 + tid] = pf[j].z;
                    nxt[(kl + 3) * 256 + tid] = pf[j].w;
                }
            }
            __syncthreads();
        }

        // tanh -> h2, in-place into sA (each warp touches only its own rows)
        if (wact) {
            #pragma unroll
            for (int i = 0; i < 8; i++) {
                float2 p0 = unpack2(acc[i][0]), p1 = unpack2(acc[i][1]);
                float2 p2 = unpack2(acc[i][2]), p3 = unpack2(acc[i][3]);
                float4 a = make_float4(fast_tanh(p0.x), fast_tanh(p0.y),
                                       fast_tanh(p1.x), fast_tanh(p1.y));
                float4 b = make_float4(fast_tanh(p2.x), fast_tanh(p2.y),
                                       fast_tanh(p3.x), fast_tanh(p3.y));
                int m = mg * 8 + i;
                *(float4*)&sA[m * 256 + og * 4] = a;
                *(float4*)&sA[m * 256 + og * 4 + 128] = b;
            }
        }
    }

    // ---- layer 3: 256 -> 64, linear, scatter to output ----
    if (wact) {
        ULL acc3[8];
        ULL b3 = *(const ULL*)(B3 + (size_t)e * 64 + og * 2);
        #pragma unroll
        for (int i = 0; i < 8; i++) acc3[i] = b3;

        #pragma unroll 2
        for (int k = 0; k < 256; k += 4) {
            float4 xr[8];
            #pragma unroll
            for (int i = 0; i < 8; i++)
                xr[i] = *(const float4*)&sA[(mg * 8 + i) * 256 + k];
            #pragma unroll
            for (int kk = 0; kk < 4; kk++) {
                ULL w = *(const ULL*)&sB[(k + kk) * 64 + og * 2];
                #pragma unroll
                for (int i = 0; i < 8; i++) {
                    float xv = (kk == 0) ? xr[i].x : (kk == 1) ? xr[i].y
                             : (kk == 2) ? xr[i].z : xr[i].w;
                    fma2(acc3[i], dup2(xv), w);
                }
            }
        }
        #pragma unroll
        for (int i = 0; i < 8; i++) {
            int m = mg * 8 + i;
            if (m < mrows) {
                int n = g_bucket[e * CAP + rs + m];
                *(ULL*)&Og[(size_t)n * OUT_DIM + og * 2] = acc3[i];
            }
        }
    }
}

// ---------------- launch ----------------
extern "C" void kernel_launch(void* const* d_in, const int* in_sizes, int n_in,
                              void* d_out, int out_size) {
    const float* x  = (const float*)d_in[0];
    const int*   ind = (const int*)d_in[1];
    const float* W1 = (const float*)d_in[2];
    const float* b1 = (const float*)d_in[3];
    const float* W2 = (const float*)d_in[4];
    const float* b2 = (const float*)d_in[5];
    const float* Wl = (const float*)d_in[6];
    const float* bl = (const float*)d_in[7];
    float* out = (float*)d_out;

    (void)in_sizes; (void)n_in; (void)out_size;

    cudaFuncSetAttribute(k_mlp, cudaFuncAttributeMaxDynamicSharedMemorySize, 196608);

    void* cnt_ptr = nullptr;
    cudaGetSymbolAddress(&cnt_ptr, g_cnt);
    cudaMemsetAsync(cnt_ptr, 0, NEXP * sizeof(int));

    k_fill<<<N_ROWS / THREADS, THREADS>>>(ind);
    k_mlp<<<dim3(NEXP, TILES_Y), THREADS, 196608>>>(x, W1, b1, W2, b2, Wl, bl, out);
}